// round 3
// baseline (speedup 1.0000x reference)
#include <cuda_runtime.h>
#include <math.h>
#include <stdint.h>

// Problem constants (fixed by the dataset)
#define N_NODES 100000
#define FEAT    256
#define RANK    64
#define HID     512
#define OUTD    128
#define E_EDGES 200000
#define KORD    4
#define DEG     8

// num = DEG^(1/K) = 8^0.25
#define NUMV 1.6817928305074290860f
// C1 = num / (K-1)! = num / 6
#define C1V  (NUMV / 6.0f)

// -------- scratch (device globals: the sanctioned no-alloc workaround) -----
__device__ float g_emb1[(size_t)N_NODES * RANK];   // num*(emb@Wp + bp)   25.6 MB
__device__ float g_h   [(size_t)N_NODES * HID];    // relu(emb@W1 + b1)  204.8 MB
__device__ float g_emb2[(size_t)N_NODES * OUTD];   // h@W2 + b2          51.2 MB

// ---------------------------------------------------------------------------
// Generic register-blocked SGEMM: C[M,N] = epi(A[M,K] @ B[K,N] + bias)
// EPI: 0 = none, 1 = relu, 2 = scale by alpha after bias
// Requires: K % BK == 0, N % BN == 0 (true for all three calls). M guarded.
// ---------------------------------------------------------------------------
template <int BM, int BN, int BK, int TM, int TN, int EPI>
__global__ __launch_bounds__(256) void sgemm_kernel(
    int M, int N, int K,
    const float* __restrict__ A, const float* __restrict__ B,
    const float* __restrict__ bias, float* __restrict__ C, float alpha)
{
    static_assert((BM / TM) * (BN / TN) == 256, "256 threads");
    __shared__ float As[BK][BM];   // A tile stored transposed
    __shared__ float Bs[BK][BN];

    const int tid     = threadIdx.x;
    const int tcols   = BN / TN;
    const int tr      = tid / tcols;
    const int tc      = tid % tcols;
    const int rowBase = blockIdx.y * BM;
    const int colBase = blockIdx.x * BN;

    const int aRow0 = tid / (BK / 4);
    const int aCol  = (tid % (BK / 4)) * 4;
    constexpr int ASTRIDE = 256 / (BK / 4);
    const int bRow0 = tid / (BN / 4);
    const int bCol  = (tid % (BN / 4)) * 4;
    constexpr int BSTRIDE = 256 / (BN / 4);

    float acc[TM][TN];
#pragma unroll
    for (int i = 0; i < TM; i++)
#pragma unroll
        for (int j = 0; j < TN; j++) acc[i][j] = 0.0f;

    for (int k0 = 0; k0 < K; k0 += BK) {
        // Load A tile (transposed into SMEM), guard rows beyond M
#pragma unroll
        for (int r = 0; r < BM; r += ASTRIDE) {
            const int row  = r + aRow0;
            const int grow = rowBase + row;
            float4 v = make_float4(0.f, 0.f, 0.f, 0.f);
            if (grow < M)
                v = *(const float4*)&A[(size_t)grow * K + k0 + aCol];
            As[aCol + 0][row] = v.x;
            As[aCol + 1][row] = v.y;
            As[aCol + 2][row] = v.z;
            As[aCol + 3][row] = v.w;
        }
        // Load B tile
#pragma unroll
        for (int r = 0; r < BK; r += BSTRIDE) {
            const int row = r + bRow0;
            *(float4*)&Bs[row][bCol] =
                *(const float4*)&B[(size_t)(k0 + row) * N + colBase + bCol];
        }
        __syncthreads();

#pragma unroll
        for (int kk = 0; kk < BK; kk++) {
            float ra[TM], rb[TN];
#pragma unroll
            for (int i = 0; i < TM; i += 4)
                *(float4*)&ra[i] = *(const float4*)&As[kk][tr * TM + i];
#pragma unroll
            for (int j = 0; j < TN; j += 4)
                *(float4*)&rb[j] = *(const float4*)&Bs[kk][tc * TN + j];
#pragma unroll
            for (int i = 0; i < TM; i++)
#pragma unroll
                for (int j = 0; j < TN; j++)
                    acc[i][j] += ra[i] * rb[j];
        }
        __syncthreads();
    }

    // Epilogue
#pragma unroll
    for (int i = 0; i < TM; i++) {
        const int grow = rowBase + tr * TM + i;
        if (grow >= M) continue;
#pragma unroll
        for (int j = 0; j < TN; j += 4) {
            const int gcol = colBase + tc * TN + j;
            const float4 bv = *(const float4*)&bias[gcol];
            float4 o;
            o.x = acc[i][j + 0] + bv.x;
            o.y = acc[i][j + 1] + bv.y;
            o.z = acc[i][j + 2] + bv.z;
            o.w = acc[i][j + 3] + bv.w;
            if (EPI == 1) {
                o.x = fmaxf(o.x, 0.f); o.y = fmaxf(o.y, 0.f);
                o.z = fmaxf(o.z, 0.f); o.w = fmaxf(o.w, 0.f);
            } else if (EPI == 2) {
                o.x *= alpha; o.y *= alpha; o.z *= alpha; o.w *= alpha;
            }
            *(float4*)&C[(size_t)grow * N + gcol] = o;
        }
    }
}

// ---------------------------------------------------------------------------
// Vector reduction (no return) to global: 4 channels in one instruction
// ---------------------------------------------------------------------------
__device__ __forceinline__ void red_add_v4(float* p, float4 v)
{
    asm volatile("red.global.add.v4.f32 [%0], {%1, %2, %3, %4};"
                 :: "l"(p), "f"(v.x), "f"(v.y), "f"(v.z), "f"(v.w)
                 : "memory");
}

// ---------------------------------------------------------------------------
// Edge kernel: one warp per edge (grid-stride).
//   - gather emb2 rows, sum, relu                 (edge2)
//   - gather emb1 rows, leave-one-out prod, tanh  (term[4][64] in SMEM)
//   - GEMV: term @ Wq  (Wq staged in SMEM)
//   - scatter-add contrib per member via red.v4
// Lane l owns output channels [4l, 4l+4).
// ---------------------------------------------------------------------------
__global__ __launch_bounds__(256) void edge_kernel(
    const int*   __restrict__ edges,
    const float* __restrict__ emb1,
    const float* __restrict__ emb2,
    const float4* __restrict__ Wq4,     // [RANK][OUTD/4]
    const float* __restrict__ bq,
    float* __restrict__ out)
{
    __shared__ float4 Wq_s[RANK * (OUTD / 4)];  // 32 KB
    __shared__ float4 term_s[8][RANK];          // per-warp: term[r] = (k0..k3), 8 KB
    __shared__ float  bq_s[OUTD];

    const int tid  = threadIdx.x;
    const int warp = tid >> 5;
    const int lane = tid & 31;

    for (int i = tid; i < RANK * (OUTD / 4); i += 256) Wq_s[i] = Wq4[i];
    for (int i = tid; i < OUTD; i += 256) bq_s[i] = bq[i];
    __syncthreads();

    const float4 bqv = *(const float4*)&bq_s[lane * 4];

    const int stride = gridDim.x * 8;
    for (int e = blockIdx.x * 8 + warp; e < E_EDGES; e += stride) {
        const int4 idx = *(const int4*)&edges[e * 4];

        // edge2 = relu(sum_k emb2[idx_k])  -- lane's 4 channels
        float4 a0 = *(const float4*)&emb2[(size_t)idx.x * OUTD + lane * 4];
        float4 a1 = *(const float4*)&emb2[(size_t)idx.y * OUTD + lane * 4];
        float4 a2 = *(const float4*)&emb2[(size_t)idx.z * OUTD + lane * 4];
        float4 a3 = *(const float4*)&emb2[(size_t)idx.w * OUTD + lane * 4];
        float4 s2;
        s2.x = fmaxf(a0.x + a1.x + a2.x + a3.x, 0.f);
        s2.y = fmaxf(a0.y + a1.y + a2.y + a3.y, 0.f);
        s2.z = fmaxf(a0.z + a1.z + a2.z + a3.z, 0.f);
        s2.w = fmaxf(a0.w + a1.w + a2.w + a3.w, 0.f);

        // term[k][r] = tanh(C1 * prod_{j!=k} g_j[r]); 2 r-values per lane
#pragma unroll
        for (int rr = 0; rr < 2; rr++) {
            const int r = lane + rr * 32;
            const float g0 = emb1[(size_t)idx.x * RANK + r];
            const float g1 = emb1[(size_t)idx.y * RANK + r];
            const float g2 = emb1[(size_t)idx.z * RANK + r];
            const float g3 = emb1[(size_t)idx.w * RANK + r];
            const float a01 = g0 * g1, a23 = g2 * g3;
            float4 t;
            t.x = tanhf(C1V * (g1 * a23));
            t.y = tanhf(C1V * (g0 * a23));
            t.z = tanhf(C1V * (a01 * g3));
            t.w = tanhf(C1V * (a01 * g2));
            term_s[warp][r] = t;
        }
        __syncwarp();

        // GEMV: acc_k[c] = sum_r term[k][r] * Wq[r][c], lane's 4 channels
        float4 acc0 = make_float4(0.f, 0.f, 0.f, 0.f);
        float4 acc1 = acc0, acc2 = acc0, acc3 = acc0;
#pragma unroll
        for (int r = 0; r < RANK; r++) {
            const float4 t = term_s[warp][r];   // broadcast
            const float4 w = Wq_s[r * (OUTD / 4) + lane];
            acc0.x += t.x * w.x; acc0.y += t.x * w.y; acc0.z += t.x * w.z; acc0.w += t.x * w.w;
            acc1.x += t.y * w.x; acc1.y += t.y * w.y; acc1.z += t.y * w.z; acc1.w += t.y * w.w;
            acc2.x += t.z * w.x; acc2.y += t.z * w.y; acc2.z += t.z * w.z; acc2.w += t.z * w.w;
            acc3.x += t.w * w.x; acc3.y += t.w * w.y; acc3.z += t.w * w.z; acc3.w += t.w * w.w;
        }

        float4 base;
        base.x = bqv.x + s2.x; base.y = bqv.y + s2.y;
        base.z = bqv.z + s2.z; base.w = bqv.w + s2.w;

        float4 v;
        v.x = acc0.x + base.x; v.y = acc0.y + base.y; v.z = acc0.z + base.z; v.w = acc0.w + base.w;
        red_add_v4(&out[(size_t)idx.x * OUTD + lane * 4], v);
        v.x = acc1.x + base.x; v.y = acc1.y + base.y; v.z = acc1.z + base.z; v.w = acc1.w + base.w;
        red_add_v4(&out[(size_t)idx.y * OUTD + lane * 4], v);
        v.x = acc2.x + base.x; v.y = acc2.y + base.y; v.z = acc2.z + base.z; v.w = acc2.w + base.w;
        red_add_v4(&out[(size_t)idx.z * OUTD + lane * 4], v);
        v.x = acc3.x + base.x; v.y = acc3.y + base.y; v.z = acc3.z + base.z; v.w = acc3.w + base.w;
        red_add_v4(&out[(size_t)idx.w * OUTD + lane * 4], v);

        __syncwarp();   // protect term_s before next iteration's writes
    }
}

// ---------------------------------------------------------------------------
__global__ void zero_kernel(float4* __restrict__ p, int n4)
{
    const float4 z = make_float4(0.f, 0.f, 0.f, 0.f);
    for (int i = blockIdx.x * blockDim.x + threadIdx.x; i < n4;
         i += gridDim.x * blockDim.x)
        p[i] = z;
}

__global__ void finalize_kernel(float4* __restrict__ p, int n4)
{
    for (int i = blockIdx.x * blockDim.x + threadIdx.x; i < n4;
         i += gridDim.x * blockDim.x) {
        float4 v = p[i];
        v.x = fmaxf(v.x * 0.125f, 0.f);
        v.y = fmaxf(v.y * 0.125f, 0.f);
        v.z = fmaxf(v.z * 0.125f, 0.f);
        v.w = fmaxf(v.w * 0.125f, 0.f);
        p[i] = v;
    }
}

// ---------------------------------------------------------------------------
extern "C" void kernel_launch(void* const* d_in, const int* in_sizes, int n_in,
                              void* d_out, int out_size)
{
    const float* emb   = (const float*)d_in[0];
    const float* Wp    = (const float*)d_in[1];
    const float* bp    = (const float*)d_in[2];
    const float* Wq    = (const float*)d_in[3];
    const float* bq    = (const float*)d_in[4];
    const float* W1    = (const float*)d_in[5];
    const float* b1    = (const float*)d_in[6];
    const float* W2    = (const float*)d_in[7];
    const float* b2    = (const float*)d_in[8];
    const int*   edges = (const int*)d_in[9];
    float* out = (float*)d_out;

    float *p_emb1, *p_h, *p_emb2;
    cudaGetSymbolAddress((void**)&p_emb1, g_emb1);
    cudaGetSymbolAddress((void**)&p_h,    g_h);
    cudaGetSymbolAddress((void**)&p_emb2, g_emb2);

    const int n4 = out_size / 4;  // N*OUTD/4 float4s

    // 1) zero the accumulator (d_out)
    zero_kernel<<<2048, 256>>>((float4*)out, n4);

    const int grid_m = (N_NODES + 127) / 128;  // 782

    // 2) emb1_scaled = num * (emb @ Wp + bp)        [1e5, 64]
    sgemm_kernel<128, 64, 16, 8, 4, 2><<<dim3(1, grid_m), 256>>>(
        N_NODES, RANK, FEAT, emb, Wp, bp, p_emb1, NUMV);

    // 3) h = relu(emb @ W1 + b1)                    [1e5, 512]
    sgemm_kernel<128, 128, 16, 8, 8, 1><<<dim3(HID / 128, grid_m), 256>>>(
        N_NODES, HID, FEAT, emb, W1, b1, p_h, 1.0f);

    // 4) emb2 = h @ W2 + b2                         [1e5, 128]
    sgemm_kernel<128, 128, 16, 8, 8, 0><<<dim3(1, grid_m), 256>>>(
        N_NODES, OUTD, HID, p_h, W2, b2, p_emb2, 1.0f);

    // 5) edge stage: gather, exclusive-prod, tanh, GEMV, scatter-add
    edge_kernel<<<740, 256>>>(edges, p_emb1, p_emb2,
                              (const float4*)Wq, bq, out);

    // 6) out = relu(out / DEG)
    finalize_kernel<<<2048, 256>>>((float4*)out, n4);
}

// round 4
// speedup vs baseline: 1.0010x; 1.0010x over previous
#include <cuda_runtime.h>
#include <math.h>
#include <stdint.h>

// Problem constants (fixed by the dataset)
#define N_NODES 100000
#define FEAT    256
#define RANK    64
#define HID     512
#define OUTD    128
#define E_EDGES 200000
#define KORD    4
#define DEG     8

// num = DEG^(1/K) = 8^0.25
#define NUMV 1.6817928305074290860f
// C1 = num / (K-1)! = num / 6
#define C1V  (NUMV / 6.0f)

// -------- scratch (device globals: the sanctioned no-alloc workaround) -----
__device__ float g_emb1[(size_t)N_NODES * RANK];   // num*(emb@Wp + bp)   25.6 MB
__device__ float g_h   [(size_t)N_NODES * HID];    // relu(emb@W1 + b1)  204.8 MB
__device__ float g_emb2[(size_t)N_NODES * OUTD];   // h@W2 + b2          51.2 MB

// ---------------------------------------------------------------------------
// Generic register-blocked SGEMM: C[M,N] = epi(A[M,K] @ B[K,N] + bias)
// EPI: 0 = none, 1 = relu, 2 = scale by alpha after bias
// Requires: K % BK == 0, N % BN == 0 (true for all three calls). M guarded.
// ---------------------------------------------------------------------------
template <int BM, int BN, int BK, int TM, int TN, int EPI>
__global__ __launch_bounds__(256) void sgemm_kernel(
    int M, int N, int K,
    const float* __restrict__ A, const float* __restrict__ B,
    const float* __restrict__ bias, float* __restrict__ C, float alpha)
{
    static_assert((BM / TM) * (BN / TN) == 256, "256 threads");
    __shared__ float As[BK][BM];   // A tile stored transposed
    __shared__ float Bs[BK][BN];

    const int tid     = threadIdx.x;
    const int tcols   = BN / TN;
    const int tr      = tid / tcols;
    const int tc      = tid % tcols;
    const int rowBase = blockIdx.y * BM;
    const int colBase = blockIdx.x * BN;

    const int aRow0 = tid / (BK / 4);
    const int aCol  = (tid % (BK / 4)) * 4;
    constexpr int ASTRIDE = 256 / (BK / 4);
    const int bRow0 = tid / (BN / 4);
    const int bCol  = (tid % (BN / 4)) * 4;
    constexpr int BSTRIDE = 256 / (BN / 4);

    float acc[TM][TN];
#pragma unroll
    for (int i = 0; i < TM; i++)
#pragma unroll
        for (int j = 0; j < TN; j++) acc[i][j] = 0.0f;

    for (int k0 = 0; k0 < K; k0 += BK) {
        // Load A tile (transposed into SMEM), guard rows beyond M
#pragma unroll
        for (int r = 0; r < BM; r += ASTRIDE) {
            const int row  = r + aRow0;
            const int grow = rowBase + row;
            float4 v = make_float4(0.f, 0.f, 0.f, 0.f);
            if (grow < M)
                v = *(const float4*)&A[(size_t)grow * K + k0 + aCol];
            As[aCol + 0][row] = v.x;
            As[aCol + 1][row] = v.y;
            As[aCol + 2][row] = v.z;
            As[aCol + 3][row] = v.w;
        }
        // Load B tile
#pragma unroll
        for (int r = 0; r < BK; r += BSTRIDE) {
            const int row = r + bRow0;
            *(float4*)&Bs[row][bCol] =
                *(const float4*)&B[(size_t)(k0 + row) * N + colBase + bCol];
        }
        __syncthreads();

#pragma unroll
        for (int kk = 0; kk < BK; kk++) {
            float ra[TM], rb[TN];
#pragma unroll
            for (int i = 0; i < TM; i += 4)
                *(float4*)&ra[i] = *(const float4*)&As[kk][tr * TM + i];
#pragma unroll
            for (int j = 0; j < TN; j += 4)
                *(float4*)&rb[j] = *(const float4*)&Bs[kk][tc * TN + j];
#pragma unroll
            for (int i = 0; i < TM; i++)
#pragma unroll
                for (int j = 0; j < TN; j++)
                    acc[i][j] += ra[i] * rb[j];
        }
        __syncthreads();
    }

    // Epilogue
#pragma unroll
    for (int i = 0; i < TM; i++) {
        const int grow = rowBase + tr * TM + i;
        if (grow >= M) continue;
#pragma unroll
        for (int j = 0; j < TN; j += 4) {
            const int gcol = colBase + tc * TN + j;
            const float4 bv = *(const float4*)&bias[gcol];
            float4 o;
            o.x = acc[i][j + 0] + bv.x;
            o.y = acc[i][j + 1] + bv.y;
            o.z = acc[i][j + 2] + bv.z;
            o.w = acc[i][j + 3] + bv.w;
            if (EPI == 1) {
                o.x = fmaxf(o.x, 0.f); o.y = fmaxf(o.y, 0.f);
                o.z = fmaxf(o.z, 0.f); o.w = fmaxf(o.w, 0.f);
            } else if (EPI == 2) {
                o.x *= alpha; o.y *= alpha; o.z *= alpha; o.w *= alpha;
            }
            *(float4*)&C[(size_t)grow * N + gcol] = o;
        }
    }
}

// ---------------------------------------------------------------------------
// Vector reduction (no return) to global: 4 channels in one instruction
// ---------------------------------------------------------------------------
__device__ __forceinline__ void red_add_v4(float* p, float4 v)
{
    asm volatile("red.global.add.v4.f32 [%0], {%1, %2, %3, %4};"
                 :: "l"(p), "f"(v.x), "f"(v.y), "f"(v.z), "f"(v.w)
                 : "memory");
}

// ---------------------------------------------------------------------------
// Edge kernel: one warp per edge (grid-stride).
//   - gather emb2 rows, sum, relu                 (edge2)
//   - gather emb1 rows, leave-one-out prod, tanh  (term[4][64] in SMEM)
//   - GEMV: term @ Wq  (Wq staged in SMEM)
//   - scatter-add contrib per member via red.v4
// Lane l owns output channels [4l, 4l+4).
// ---------------------------------------------------------------------------
__global__ __launch_bounds__(256) void edge_kernel(
    const int*   __restrict__ edges,
    const float* __restrict__ emb1,
    const float* __restrict__ emb2,
    const float4* __restrict__ Wq4,     // [RANK][OUTD/4]
    const float* __restrict__ bq,
    float* __restrict__ out)
{
    __shared__ float4 Wq_s[RANK * (OUTD / 4)];  // 32 KB
    __shared__ float4 term_s[8][RANK];          // per-warp: term[r] = (k0..k3), 8 KB
    __shared__ float  bq_s[OUTD];

    const int tid  = threadIdx.x;
    const int warp = tid >> 5;
    const int lane = tid & 31;

    for (int i = tid; i < RANK * (OUTD / 4); i += 256) Wq_s[i] = Wq4[i];
    for (int i = tid; i < OUTD; i += 256) bq_s[i] = bq[i];
    __syncthreads();

    const float4 bqv = *(const float4*)&bq_s[lane * 4];

    const int stride = gridDim.x * 8;
    for (int e = blockIdx.x * 8 + warp; e < E_EDGES; e += stride) {
        const int4 idx = *(const int4*)&edges[e * 4];

        // edge2 = relu(sum_k emb2[idx_k])  -- lane's 4 channels
        float4 a0 = *(const float4*)&emb2[(size_t)idx.x * OUTD + lane * 4];
        float4 a1 = *(const float4*)&emb2[(size_t)idx.y * OUTD + lane * 4];
        float4 a2 = *(const float4*)&emb2[(size_t)idx.z * OUTD + lane * 4];
        float4 a3 = *(const float4*)&emb2[(size_t)idx.w * OUTD + lane * 4];
        float4 s2;
        s2.x = fmaxf(a0.x + a1.x + a2.x + a3.x, 0.f);
        s2.y = fmaxf(a0.y + a1.y + a2.y + a3.y, 0.f);
        s2.z = fmaxf(a0.z + a1.z + a2.z + a3.z, 0.f);
        s2.w = fmaxf(a0.w + a1.w + a2.w + a3.w, 0.f);

        // term[k][r] = tanh(C1 * prod_{j!=k} g_j[r]); 2 r-values per lane
#pragma unroll
        for (int rr = 0; rr < 2; rr++) {
            const int r = lane + rr * 32;
            const float g0 = emb1[(size_t)idx.x * RANK + r];
            const float g1 = emb1[(size_t)idx.y * RANK + r];
            const float g2 = emb1[(size_t)idx.z * RANK + r];
            const float g3 = emb1[(size_t)idx.w * RANK + r];
            const float a01 = g0 * g1, a23 = g2 * g3;
            float4 t;
            t.x = tanhf(C1V * (g1 * a23));
            t.y = tanhf(C1V * (g0 * a23));
            t.z = tanhf(C1V * (a01 * g3));
            t.w = tanhf(C1V * (a01 * g2));
            term_s[warp][r] = t;
        }
        __syncwarp();

        // GEMV: acc_k[c] = sum_r term[k][r] * Wq[r][c], lane's 4 channels
        float4 acc0 = make_float4(0.f, 0.f, 0.f, 0.f);
        float4 acc1 = acc0, acc2 = acc0, acc3 = acc0;
#pragma unroll
        for (int r = 0; r < RANK; r++) {
            const float4 t = term_s[warp][r];   // broadcast
            const float4 w = Wq_s[r * (OUTD / 4) + lane];
            acc0.x += t.x * w.x; acc0.y += t.x * w.y; acc0.z += t.x * w.z; acc0.w += t.x * w.w;
            acc1.x += t.y * w.x; acc1.y += t.y * w.y; acc1.z += t.y * w.z; acc1.w += t.y * w.w;
            acc2.x += t.z * w.x; acc2.y += t.z * w.y; acc2.z += t.z * w.z; acc2.w += t.z * w.w;
            acc3.x += t.w * w.x; acc3.y += t.w * w.y; acc3.z += t.w * w.z; acc3.w += t.w * w.w;
        }

        float4 base;
        base.x = bqv.x + s2.x; base.y = bqv.y + s2.y;
        base.z = bqv.z + s2.z; base.w = bqv.w + s2.w;

        float4 v;
        v.x = acc0.x + base.x; v.y = acc0.y + base.y; v.z = acc0.z + base.z; v.w = acc0.w + base.w;
        red_add_v4(&out[(size_t)idx.x * OUTD + lane * 4], v);
        v.x = acc1.x + base.x; v.y = acc1.y + base.y; v.z = acc1.z + base.z; v.w = acc1.w + base.w;
        red_add_v4(&out[(size_t)idx.y * OUTD + lane * 4], v);
        v.x = acc2.x + base.x; v.y = acc2.y + base.y; v.z = acc2.z + base.z; v.w = acc2.w + base.w;
        red_add_v4(&out[(size_t)idx.z * OUTD + lane * 4], v);
        v.x = acc3.x + base.x; v.y = acc3.y + base.y; v.z = acc3.z + base.z; v.w = acc3.w + base.w;
        red_add_v4(&out[(size_t)idx.w * OUTD + lane * 4], v);

        __syncwarp();   // protect term_s before next iteration's writes
    }
}

// ---------------------------------------------------------------------------
__global__ void zero_kernel(float4* __restrict__ p, int n4)
{
    const float4 z = make_float4(0.f, 0.f, 0.f, 0.f);
    for (int i = blockIdx.x * blockDim.x + threadIdx.x; i < n4;
         i += gridDim.x * blockDim.x)
        p[i] = z;
}

__global__ void finalize_kernel(float4* __restrict__ p, int n4)
{
    for (int i = blockIdx.x * blockDim.x + threadIdx.x; i < n4;
         i += gridDim.x * blockDim.x) {
        float4 v = p[i];
        v.x = fmaxf(v.x * 0.125f, 0.f);
        v.y = fmaxf(v.y * 0.125f, 0.f);
        v.z = fmaxf(v.z * 0.125f, 0.f);
        v.w = fmaxf(v.w * 0.125f, 0.f);
        p[i] = v;
    }
}

// ---------------------------------------------------------------------------
extern "C" void kernel_launch(void* const* d_in, const int* in_sizes, int n_in,
                              void* d_out, int out_size)
{
    const float* emb   = (const float*)d_in[0];
    const float* Wp    = (const float*)d_in[1];
    const float* bp    = (const float*)d_in[2];
    const float* Wq    = (const float*)d_in[3];
    const float* bq    = (const float*)d_in[4];
    const float* W1    = (const float*)d_in[5];
    const float* b1    = (const float*)d_in[6];
    const float* W2    = (const float*)d_in[7];
    const float* b2    = (const float*)d_in[8];
    const int*   edges = (const int*)d_in[9];
    float* out = (float*)d_out;

    float *p_emb1, *p_h, *p_emb2;
    cudaGetSymbolAddress((void**)&p_emb1, g_emb1);
    cudaGetSymbolAddress((void**)&p_h,    g_h);
    cudaGetSymbolAddress((void**)&p_emb2, g_emb2);

    const int n4 = out_size / 4;  // N*OUTD/4 float4s

    // 1) zero the accumulator (d_out)
    zero_kernel<<<2048, 256>>>((float4*)out, n4);

    const int grid_m = (N_NODES + 127) / 128;  // 782

    // 2) emb1_scaled = num * (emb @ Wp + bp)        [1e5, 64]
    sgemm_kernel<128, 64, 16, 8, 4, 2><<<dim3(1, grid_m), 256>>>(
        N_NODES, RANK, FEAT, emb, Wp, bp, p_emb1, NUMV);

    // 3) h = relu(emb @ W1 + b1)                    [1e5, 512]
    sgemm_kernel<128, 128, 16, 8, 8, 1><<<dim3(HID / 128, grid_m), 256>>>(
        N_NODES, HID, FEAT, emb, W1, b1, p_h, 1.0f);

    // 4) emb2 = h @ W2 + b2                         [1e5, 128]
    sgemm_kernel<128, 128, 16, 8, 8, 0><<<dim3(1, grid_m), 256>>>(
        N_NODES, OUTD, HID, p_h, W2, b2, p_emb2, 1.0f);

    // 5) edge stage: gather, exclusive-prod, tanh, GEMV, scatter-add
    edge_kernel<<<740, 256>>>(edges, p_emb1, p_emb2,
                              (const float4*)Wq, bq, out);

    // 6) out = relu(out / DEG)
    finalize_kernel<<<2048, 256>>>((float4*)out, n4);
}